// round 6
// baseline (speedup 1.0000x reference)
#include <cuda_runtime.h>
#include <cuda_bf16.h>
#include <math.h>
#include <stdint.h>

#define B_DIM 4096
#define IN_DIM 512
#define H_DIM 1024
#define NGATE (4 * H_DIM)          // 4096
#define KTOT  (IN_DIM + H_DIM)     // 1536
#define KC 64                      // K per stage (bf16)
#define NSTAGE (KTOT / KC)         // 24

// bf16 hi/lo split copies of A = [input | hx] and B = permuted [Wxh | Whh]
__device__ __align__(16) __nv_bfloat16 g_Ah[(size_t)B_DIM * KTOT];
__device__ __align__(16) __nv_bfloat16 g_Al[(size_t)B_DIM * KTOT];
__device__ __align__(16) __nv_bfloat16 g_Bh[(size_t)NGATE * KTOT];
__device__ __align__(16) __nv_bfloat16 g_Bl[(size_t)NGATE * KTOT];

// ---------------- asm helpers (sm_80-compatible PTX only) ----------------

__device__ __forceinline__ uint32_t smem_u32(const void* p) {
    uint32_t a;
    asm("{ .reg .u64 t; cvta.to.shared.u64 t, %1; cvt.u32.u64 %0, t; }"
        : "=r"(a) : "l"(p));
    return a;
}

__device__ __forceinline__ void cpasync16(uint32_t dst, const void* src) {
    asm volatile("cp.async.cg.shared.global [%0], [%1], 16;"
                 :: "r"(dst), "l"(__cvta_generic_to_global(src)) : "memory");
}
#define CP_COMMIT() asm volatile("cp.async.commit_group;" ::: "memory")
#define CP_WAIT(n)  asm volatile("cp.async.wait_group %0;" :: "n"(n) : "memory")

__device__ __forceinline__ void ldsm_x4(uint32_t& r0, uint32_t& r1,
                                        uint32_t& r2, uint32_t& r3, uint32_t a) {
    asm volatile("ldmatrix.sync.aligned.m8n8.x4.shared.b16 {%0,%1,%2,%3}, [%4];"
                 : "=r"(r0), "=r"(r1), "=r"(r2), "=r"(r3) : "r"(a));
}

__device__ __forceinline__ void mma_bf16(float* d, const uint32_t* a,
                                         const uint32_t* b) {
    asm volatile(
        "mma.sync.aligned.m16n8k16.row.col.f32.bf16.bf16.f32 "
        "{%0,%1,%2,%3}, {%4,%5,%6,%7}, {%8,%9}, {%0,%1,%2,%3};"
        : "+f"(d[0]), "+f"(d[1]), "+f"(d[2]), "+f"(d[3])
        : "r"(a[0]), "r"(a[1]), "r"(a[2]), "r"(a[3]), "r"(b[0]), "r"(b[1]));
}

// ---------------- fused prep kernel ----------------

struct alignas(16) Bf8 { __nv_bfloat16 h[8]; };

__device__ __forceinline__ void split8(const float* f, Bf8& hi, Bf8& lo) {
#pragma unroll
    for (int e = 0; e < 8; e++) {
        __nv_bfloat16 h = __float2bfloat16_rn(f[e]);
        hi.h[e] = h;
        lo.h[e] = __float2bfloat16_rn(f[e] - __bfloat162float(h));
    }
}

// blocks [0,3072): A rows; blocks [3072,6144): B rows (permuted)
__global__ __launch_bounds__(256) void prep_kernel(
    const float* __restrict__ input, const float* __restrict__ hx,
    const float* __restrict__ Wxh, const float* __restrict__ Whh)
{
    int bid = blockIdx.x;
    if (bid < 3072) {
        int idx = bid * 256 + threadIdx.x;
        int row = idx / 192;
        int k = (idx % 192) * 8;
        const float* src = (k < IN_DIM) ? (input + (size_t)row * IN_DIM + k)
                                        : (hx + (size_t)row * H_DIM + (k - IN_DIM));
        float f[8];
        float4 v0 = ((const float4*)src)[0];
        float4 v1 = ((const float4*)src)[1];
        f[0]=v0.x; f[1]=v0.y; f[2]=v0.z; f[3]=v0.w;
        f[4]=v1.x; f[5]=v1.y; f[6]=v1.z; f[7]=v1.w;
        Bf8 hi, lo; split8(f, hi, lo);
        *(uint4*)&g_Ah[(size_t)row * KTOT + k] = *(const uint4*)&hi;
        *(uint4*)&g_Al[(size_t)row * KTOT + k] = *(const uint4*)&lo;
    } else {
        int idx = (bid - 3072) * 256 + threadIdx.x;
        int rowp = idx / 192;                 // row' = (h>>3)*32 + g*8 + (h&7)
        int k = (idx % 192) * 8;
        int g = (rowp >> 3) & 3;
        int h = ((rowp >> 5) << 3) | (rowp & 7);
        int orig = g * H_DIM + h;
        const float* src = (k < IN_DIM) ? (Wxh + (size_t)orig * IN_DIM + k)
                                        : (Whh + (size_t)orig * H_DIM + (k - IN_DIM));
        float f[8];
        float4 v0 = ((const float4*)src)[0];
        float4 v1 = ((const float4*)src)[1];
        f[0]=v0.x; f[1]=v0.y; f[2]=v0.z; f[3]=v0.w;
        f[4]=v1.x; f[5]=v1.y; f[6]=v1.z; f[7]=v1.w;
        Bf8 hi, lo; split8(f, hi, lo);
        *(uint4*)&g_Bh[(size_t)rowp * KTOT + k] = *(const uint4*)&hi;
        *(uint4*)&g_Bl[(size_t)rowp * KTOT + k] = *(const uint4*)&lo;
    }
}

// ---------------- fused HMMA GEMM + phased-LSTM epilogue ----------------

#define ROW_B 144                      // 128B data + 16B pad (conflict-free)
#define TILE_SZ (128 * ROW_B)          // 18432
#define STAGE_SZ (4 * TILE_SZ)         // Ah, Al, Bh, Bl = 73728
#define NRING 3
#define SMEM_BYTES (NRING * STAGE_SZ)  // 221184

__device__ __forceinline__ float sigf(float x) { return 1.0f / (1.0f + expf(-x)); }

__global__ __launch_bounds__(512, 1) void gemm_fused_kernel(
    const float* __restrict__ time_,  // [B]
    const float* __restrict__ cx,     // [B, H]
    const float* __restrict__ tau,
    const float* __restrict__ s,
    const float* __restrict__ alpha_p,
    const float* __restrict__ rho_p,
    const float* __restrict__ bias,   // [4H]
    float* __restrict__ out)          // hy then cy
{
    extern __shared__ char smem[];
    const uint32_t sb = smem_u32(smem);
    const int tid = threadIdx.x;
    const int wid = tid >> 5;
    const int lane = tid & 31;
    const int wm = wid >> 2;          // 0..3  warp M base = wm*32
    const int wn = wid & 3;           // 0..3  warp N base = wn*32

    const int m0 = blockIdx.y * 128;
    const int n0 = blockIdx.x * 128;

    // --- global-load mapping: 1024 uint4 per tile, 2 per thread per tile ---
    const int g_row = tid >> 2;        // 0..127
    const int g_c4  = tid & 3;         // 0..3 (of 8 uint4 per row; +4 second)
    const uint32_t st_off  = (uint32_t)g_row * ROW_B + g_c4 * 16;
    const uint32_t st_off2 = st_off + 64;          // +4 uint4
    const int g_kelem  = g_c4 * 8;
    const int g_kelem2 = g_kelem + 32;

    const __nv_bfloat16* pAh = g_Ah + (size_t)(m0 + g_row) * KTOT;
    const __nv_bfloat16* pAl = g_Al + (size_t)(m0 + g_row) * KTOT;
    const __nv_bfloat16* pBh = g_Bh + (size_t)(n0 + g_row) * KTOT;
    const __nv_bfloat16* pBl = g_Bl + (size_t)(n0 + g_row) * KTOT;

    // --- ldmatrix lane offsets ---
    const int l15 = lane & 15;
    uint32_t a_off[2];
#pragma unroll
    for (int i = 0; i < 2; i++)
        a_off[i] = (uint32_t)(wm * 32 + i * 16 + l15) * ROW_B + (lane >> 4) * 16;
    uint32_t b_off[2];
    {
        int l7 = lane & 7;
        int rhalf = (lane >> 4) & 1;
        int chalf = (lane >> 3) & 1;
#pragma unroll
        for (int j = 0; j < 2; j++)
            b_off[j] = (uint32_t)(wn * 32 + j * 16 + rhalf * 8 + l7) * ROW_B + chalf * 16;
    }

    float acc[2][4][4];
#pragma unroll
    for (int i = 0; i < 2; i++)
#pragma unroll
        for (int nb = 0; nb < 4; nb++)
#pragma unroll
            for (int e = 0; e < 4; e++) acc[i][nb][e] = 0.0f;

#define ISSUE_STAGE(C, BUF) do {                                            \
    uint32_t base_ = sb + (uint32_t)(BUF) * STAGE_SZ;                       \
    size_t ke_ = (size_t)(C) * KC;                                          \
    cpasync16(base_ + st_off,                pAh + ke_ + g_kelem);          \
    cpasync16(base_ + st_off2,               pAh + ke_ + g_kelem2);         \
    cpasync16(base_ + TILE_SZ + st_off,      pAl + ke_ + g_kelem);          \
    cpasync16(base_ + TILE_SZ + st_off2,     pAl + ke_ + g_kelem2);         \
    cpasync16(base_ + 2*TILE_SZ + st_off,    pBh + ke_ + g_kelem);          \
    cpasync16(base_ + 2*TILE_SZ + st_off2,   pBh + ke_ + g_kelem2);         \
    cpasync16(base_ + 3*TILE_SZ + st_off,    pBl + ke_ + g_kelem);          \
    cpasync16(base_ + 3*TILE_SZ + st_off2,   pBl + ke_ + g_kelem2);         \
    CP_COMMIT();                                                            \
} while (0)

    ISSUE_STAGE(0, 0);
    ISSUE_STAGE(1, 1);

    for (int c = 0; c < NSTAGE; c++) {
        const int buf = c % 3;

        // At top of iter c, issued groups: 0..min(c+1, NSTAGE-1).
        // Allow the newest (c+1) to remain in flight; require stage c done.
        if (c + 1 < NSTAGE) { CP_WAIT(1); }
        else                { CP_WAIT(0); }

        // Barrier BEFORE issuing into buf (c+2)%3 == (c-1)%3: all warps have
        // finished reading stage c-1 (its compute preceded this barrier).
        __syncthreads();

        if (c + 2 < NSTAGE)
            ISSUE_STAGE(c + 2, (c + 2) % 3);

        const uint32_t ahb = sb + (uint32_t)buf * STAGE_SZ;
        const uint32_t alb = ahb + TILE_SZ;
        const uint32_t bhb = ahb + 2 * TILE_SZ;
        const uint32_t blb = ahb + 3 * TILE_SZ;

#pragma unroll
        for (int ks = 0; ks < 4; ks++) {
            const uint32_t ko = ks * 32;
            // hoist ALL fragment loads for this k-step, then run 24 MMAs
            uint32_t ah[2][4], al[2][4], bh[4][2], bl[4][2];
#pragma unroll
            for (int j = 0; j < 2; j++)
                ldsm_x4(bh[2*j][0], bh[2*j][1], bh[2*j+1][0], bh[2*j+1][1],
                        bhb + b_off[j] + ko);
#pragma unroll
            for (int i = 0; i < 2; i++)
                ldsm_x4(ah[i][0], ah[i][1], ah[i][2], ah[i][3],
                        ahb + a_off[i] + ko);
#pragma unroll
            for (int j = 0; j < 2; j++)
                ldsm_x4(bl[2*j][0], bl[2*j][1], bl[2*j+1][0], bl[2*j+1][1],
                        blb + b_off[j] + ko);
#pragma unroll
            for (int i = 0; i < 2; i++)
                ldsm_x4(al[i][0], al[i][1], al[i][2], al[i][3],
                        alb + a_off[i] + ko);

#pragma unroll
            for (int i = 0; i < 2; i++)
#pragma unroll
                for (int nb = 0; nb < 4; nb++)
                    mma_bf16(acc[i][nb], ah[i], bh[nb]);
#pragma unroll
            for (int i = 0; i < 2; i++)
#pragma unroll
                for (int nb = 0; nb < 4; nb++)
                    mma_bf16(acc[i][nb], ah[i], bl[nb]);
#pragma unroll
            for (int i = 0; i < 2; i++)
#pragma unroll
                for (int nb = 0; nb < 4; nb++)
                    mma_bf16(acc[i][nb], al[i], bh[nb]);
        }
    }

    // ---- fused epilogue ----
    // acc[i][nb][e]: m-row = m0 + wm*32 + i*16 + (lane>>2) + (e>>1)*8
    //                gate = nb, h = (n0 + wn*32)/4 + 2*(lane&3) + (e&1)
    const int t = lane & 3;
    const int grow = lane >> 2;
    const int hb = ((n0 + wn * 32) >> 2) + 2 * t;

    const float alpha = alpha_p[0];
    const float rho = rho_p[0];
    const float inv_rho = 2.0f / rho;
    const float tu[2] = {tau[hb], tau[hb + 1]};
    const float sh[2] = {s[hb], s[hb + 1]};
    float bi[4][2];
#pragma unroll
    for (int g = 0; g < 4; g++) {
        bi[g][0] = bias[g * H_DIM + hb];
        bi[g][1] = bias[g * H_DIM + hb + 1];
    }

#pragma unroll
    for (int i = 0; i < 2; i++) {
#pragma unroll
        for (int rsel = 0; rsel < 2; rsel++) {
            const int r = m0 + wm * 32 + i * 16 + grow + rsel * 8;
            const float tt = time_[r];
            const float2 cx2 = *(const float2*)&cx[(size_t)r * H_DIM + hb];
            const float cxa[2] = {cx2.x, cx2.y};
            float hy2[2], cy2[2];
#pragma unroll
            for (int e = 0; e < 2; e++) {
                const int d = rsel * 2 + e;
                float gi = acc[i][0][d] + bi[0][e];
                float gf = acc[i][1][d] + bi[1][e];
                float gg = acc[i][2][d] + bi[2][e];
                float go = acc[i][3][d] + bi[3][e];
                float phi = fmodf(tt - sh[e], tu[e]) / tu[e];
                float kg;
                if (phi < 0.5f * rho)      kg = phi * inv_rho;
                else if (phi < rho)        kg = 2.0f - phi * inv_rho;
                else                       kg = alpha * phi;
                float ft = sigf(gf + 1.0f - kg);
                float it = sigf(gi) * kg;
                float gt = tanhf(gg) * kg;
                float ot = sigf(go) * kg;
                float cyv = ft * cxa[e] + it * gt;
                cy2[e] = cyv;
                hy2[e] = ot * tanhf(cyv);
            }
            *(float2*)&out[(size_t)r * H_DIM + hb] = make_float2(hy2[0], hy2[1]);
            *(float2*)&out[(size_t)B_DIM * H_DIM + (size_t)r * H_DIM + hb] =
                make_float2(cy2[0], cy2[1]);
        }
    }
}

// ---------------- launch ----------------

extern "C" void kernel_launch(void* const* d_in, const int* in_sizes, int n_in,
                              void* d_out, int out_size) {
    const float* input = (const float*)d_in[0];
    const float* time_ = (const float*)d_in[1];
    const float* hx    = (const float*)d_in[2];
    const float* cx    = (const float*)d_in[3];
    const float* Wxh_w = (const float*)d_in[4];
    const float* Wxh_b = (const float*)d_in[5];
    const float* Whh_w = (const float*)d_in[6];
    const float* tau   = (const float*)d_in[7];
    const float* s     = (const float*)d_in[8];
    const float* alpha = (const float*)d_in[9];
    const float* rho   = (const float*)d_in[10];
    float* out = (float*)d_out;

    cudaFuncSetAttribute(gemm_fused_kernel,
                         cudaFuncAttributeMaxDynamicSharedMemorySize, SMEM_BYTES);

    prep_kernel<<<6144, 256>>>(input, hx, Wxh_w, Whh_w);

    dim3 grid(NGATE / 128, B_DIM / 128);   // 32 x 32
    gemm_fused_kernel<<<grid, 512, SMEM_BYTES>>>(
        time_, cx, tau, s, alpha, rho, Wxh_b, out);
}

// round 7
// speedup vs baseline: 1.0728x; 1.0728x over previous
#include <cuda_runtime.h>
#include <cuda_bf16.h>
#include <math.h>
#include <stdint.h>

#define B_DIM 4096
#define IN_DIM 512
#define H_DIM 1024
#define NGATE (4 * H_DIM)          // 4096
#define KTOT  (IN_DIM + H_DIM)     // 1536
#define KC 32                      // K per stage (bf16)
#define NSTAGE (KTOT / KC)         // 48

// bf16 hi/lo split copies of A = [input | hx] and B = permuted [Wxh | Whh]
__device__ __align__(16) __nv_bfloat16 g_Ah[(size_t)B_DIM * KTOT];
__device__ __align__(16) __nv_bfloat16 g_Al[(size_t)B_DIM * KTOT];
__device__ __align__(16) __nv_bfloat16 g_Bh[(size_t)NGATE * KTOT];
__device__ __align__(16) __nv_bfloat16 g_Bl[(size_t)NGATE * KTOT];

// ---------------- asm helpers (sm_80-compatible PTX only) ----------------

__device__ __forceinline__ uint32_t smem_u32(const void* p) {
    uint32_t a;
    asm("{ .reg .u64 t; cvta.to.shared.u64 t, %1; cvt.u32.u64 %0, t; }"
        : "=r"(a) : "l"(p));
    return a;
}

__device__ __forceinline__ void cpasync16(uint32_t dst, const void* src) {
    asm volatile("cp.async.cg.shared.global [%0], [%1], 16;"
                 :: "r"(dst), "l"(__cvta_generic_to_global(src)) : "memory");
}
#define CP_COMMIT() asm volatile("cp.async.commit_group;" ::: "memory")
#define CP_WAIT(n)  asm volatile("cp.async.wait_group %0;" :: "n"(n) : "memory")

__device__ __forceinline__ void ldsm_x4(uint32_t& r0, uint32_t& r1,
                                        uint32_t& r2, uint32_t& r3, uint32_t a) {
    asm volatile("ldmatrix.sync.aligned.m8n8.x4.shared.b16 {%0,%1,%2,%3}, [%4];"
                 : "=r"(r0), "=r"(r1), "=r"(r2), "=r"(r3) : "r"(a));
}

__device__ __forceinline__ void mma_bf16(float* d, const uint32_t* a,
                                         const uint32_t* b) {
    asm volatile(
        "mma.sync.aligned.m16n8k16.row.col.f32.bf16.bf16.f32 "
        "{%0,%1,%2,%3}, {%4,%5,%6,%7}, {%8,%9}, {%0,%1,%2,%3};"
        : "+f"(d[0]), "+f"(d[1]), "+f"(d[2]), "+f"(d[3])
        : "r"(a[0]), "r"(a[1]), "r"(a[2]), "r"(a[3]), "r"(b[0]), "r"(b[1]));
}

// ---------------- fused prep kernel ----------------

struct alignas(16) Bf8 { __nv_bfloat16 h[8]; };

__device__ __forceinline__ void split8(const float* f, Bf8& hi, Bf8& lo) {
#pragma unroll
    for (int e = 0; e < 8; e++) {
        __nv_bfloat16 h = __float2bfloat16_rn(f[e]);
        hi.h[e] = h;
        lo.h[e] = __float2bfloat16_rn(f[e] - __bfloat162float(h));
    }
}

// blocks [0,3072): A rows; blocks [3072,6144): B rows (permuted)
__global__ __launch_bounds__(256) void prep_kernel(
    const float* __restrict__ input, const float* __restrict__ hx,
    const float* __restrict__ Wxh, const float* __restrict__ Whh)
{
    int bid = blockIdx.x;
    if (bid < 3072) {
        int idx = bid * 256 + threadIdx.x;
        int row = idx / 192;
        int k = (idx % 192) * 8;
        const float* src = (k < IN_DIM) ? (input + (size_t)row * IN_DIM + k)
                                        : (hx + (size_t)row * H_DIM + (k - IN_DIM));
        float f[8];
        float4 v0 = ((const float4*)src)[0];
        float4 v1 = ((const float4*)src)[1];
        f[0]=v0.x; f[1]=v0.y; f[2]=v0.z; f[3]=v0.w;
        f[4]=v1.x; f[5]=v1.y; f[6]=v1.z; f[7]=v1.w;
        Bf8 hi, lo; split8(f, hi, lo);
        *(uint4*)&g_Ah[(size_t)row * KTOT + k] = *(const uint4*)&hi;
        *(uint4*)&g_Al[(size_t)row * KTOT + k] = *(const uint4*)&lo;
    } else {
        int idx = (bid - 3072) * 256 + threadIdx.x;
        int rowp = idx / 192;                 // row' = (h>>3)*32 + g*8 + (h&7)
        int k = (idx % 192) * 8;
        int g = (rowp >> 3) & 3;
        int h = ((rowp >> 5) << 3) | (rowp & 7);
        int orig = g * H_DIM + h;
        const float* src = (k < IN_DIM) ? (Wxh + (size_t)orig * IN_DIM + k)
                                        : (Whh + (size_t)orig * H_DIM + (k - IN_DIM));
        float f[8];
        float4 v0 = ((const float4*)src)[0];
        float4 v1 = ((const float4*)src)[1];
        f[0]=v0.x; f[1]=v0.y; f[2]=v0.z; f[3]=v0.w;
        f[4]=v1.x; f[5]=v1.y; f[6]=v1.z; f[7]=v1.w;
        Bf8 hi, lo; split8(f, hi, lo);
        *(uint4*)&g_Bh[(size_t)rowp * KTOT + k] = *(const uint4*)&hi;
        *(uint4*)&g_Bl[(size_t)rowp * KTOT + k] = *(const uint4*)&lo;
    }
}

// ---------------- fused HMMA GEMM + phased-LSTM epilogue ----------------
// CTA tile 128(M) x 64(N), 8 warps (warp tile 32x32), 2 CTAs/SM.

#define ROW_B 80                       // 64B data + 16B pad (conflict-free)
#define ATILE (128 * ROW_B)            // 10240
#define BTILE (64 * ROW_B)             // 5120
#define STAGE_SZ (2 * ATILE + 2 * BTILE)   // 30720
#define NRING 3
#define SMEM_BYTES (NRING * STAGE_SZ)  // 92160

__device__ __forceinline__ float sigf(float x) { return 1.0f / (1.0f + expf(-x)); }

__global__ __launch_bounds__(256, 2) void gemm_fused_kernel(
    const float* __restrict__ time_,  // [B]
    const float* __restrict__ cx,     // [B, H]
    const float* __restrict__ tau,
    const float* __restrict__ s,
    const float* __restrict__ alpha_p,
    const float* __restrict__ rho_p,
    const float* __restrict__ bias,   // [4H]
    float* __restrict__ out)          // hy then cy
{
    extern __shared__ char smem[];
    const uint32_t sb = smem_u32(smem);
    const int tid = threadIdx.x;
    const int wid = tid >> 5;
    const int lane = tid & 31;
    const int wm = wid >> 1;          // 0..3  warp M base = wm*32
    const int wn = wid & 1;           // 0..1  warp N base = wn*32

    const int m0 = blockIdx.y * 128;
    const int n0 = blockIdx.x * 64;

    // --- global-load mapping ---
    // A tiles: 128 rows x 4 uint4; 256 threads -> rows tid>>2 and +64.
    // B tiles: 64 rows x 4 uint4; 256 threads -> row tid>>2, 1 uint4 each.
    const int g_row = tid >> 2;        // 0..63
    const int g_c4  = tid & 3;         // 0..3
    const uint32_t st_off   = (uint32_t)g_row * ROW_B + g_c4 * 16;
    const uint32_t st_off64 = st_off + 64 * ROW_B;
    const int g_kelem = g_c4 * 8;

    const __nv_bfloat16* pAh  = g_Ah + (size_t)(m0 + g_row) * KTOT + g_kelem;
    const __nv_bfloat16* pAl  = g_Al + (size_t)(m0 + g_row) * KTOT + g_kelem;
    const size_t row64 = (size_t)64 * KTOT;
    const __nv_bfloat16* pBh  = g_Bh + (size_t)(n0 + g_row) * KTOT + g_kelem;
    const __nv_bfloat16* pBl  = g_Bl + (size_t)(n0 + g_row) * KTOT + g_kelem;

    // --- ldmatrix lane offsets ---
    const int l15 = lane & 15;
    uint32_t a_off[2];
#pragma unroll
    for (int i = 0; i < 2; i++)
        a_off[i] = (uint32_t)(wm * 32 + i * 16 + l15) * ROW_B + (lane >> 4) * 16;
    uint32_t b_off[2];
    {
        int l7 = lane & 7;
        int rhalf = (lane >> 4) & 1;
        int chalf = (lane >> 3) & 1;
#pragma unroll
        for (int j = 0; j < 2; j++)
            b_off[j] = (uint32_t)(wn * 32 + j * 16 + rhalf * 8 + l7) * ROW_B + chalf * 16;
    }

    float acc[2][4][4];
#pragma unroll
    for (int i = 0; i < 2; i++)
#pragma unroll
        for (int nb = 0; nb < 4; nb++)
#pragma unroll
            for (int e = 0; e < 4; e++) acc[i][nb][e] = 0.0f;

#define ISSUE_STAGE(C, BUF) do {                                            \
    uint32_t base_ = sb + (uint32_t)(BUF) * STAGE_SZ;                       \
    size_t ke_ = (size_t)(C) * KC;                                          \
    cpasync16(base_ + st_off,                      pAh + ke_);              \
    cpasync16(base_ + st_off64,                    pAh + row64 + ke_);      \
    cpasync16(base_ + ATILE + st_off,              pAl + ke_);              \
    cpasync16(base_ + ATILE + st_off64,            pAl + row64 + ke_);      \
    cpasync16(base_ + 2*ATILE + st_off,            pBh + ke_);              \
    cpasync16(base_ + 2*ATILE + BTILE + st_off,    pBl + ke_);              \
    CP_COMMIT();                                                            \
} while (0)

    ISSUE_STAGE(0, 0);
    ISSUE_STAGE(1, 1);

    for (int c = 0; c < NSTAGE; c++) {
        const int buf = c % 3;

        // Pending groups at top of iter c: {c, c+1}; require stage c done.
        if (c + 1 < NSTAGE) { CP_WAIT(1); }
        else                { CP_WAIT(0); }

        // Barrier BEFORE issuing into buf (c+2)%3 == (c-1)%3: all warps have
        // finished reading stage c-1 (its compute preceded this barrier).
        __syncthreads();

        if (c + 2 < NSTAGE)
            ISSUE_STAGE(c + 2, (c + 2) % 3);

        const uint32_t ahb = sb + (uint32_t)buf * STAGE_SZ;
        const uint32_t alb = ahb + ATILE;
        const uint32_t bhb = ahb + 2 * ATILE;
        const uint32_t blb = bhb + BTILE;

#pragma unroll
        for (int ks = 0; ks < 2; ks++) {
            const uint32_t ko = ks * 32;
            uint32_t ah[2][4], al[2][4], bh[4][2], bl[4][2];
#pragma unroll
            for (int j = 0; j < 2; j++)
                ldsm_x4(bh[2*j][0], bh[2*j][1], bh[2*j+1][0], bh[2*j+1][1],
                        bhb + b_off[j] + ko);
#pragma unroll
            for (int i = 0; i < 2; i++)
                ldsm_x4(ah[i][0], ah[i][1], ah[i][2], ah[i][3],
                        ahb + a_off[i] + ko);
#pragma unroll
            for (int j = 0; j < 2; j++)
                ldsm_x4(bl[2*j][0], bl[2*j][1], bl[2*j+1][0], bl[2*j+1][1],
                        blb + b_off[j] + ko);
#pragma unroll
            for (int i = 0; i < 2; i++)
                ldsm_x4(al[i][0], al[i][1], al[i][2], al[i][3],
                        alb + a_off[i] + ko);

#pragma unroll
            for (int i = 0; i < 2; i++)
#pragma unroll
                for (int nb = 0; nb < 4; nb++)
                    mma_bf16(acc[i][nb], ah[i], bh[nb]);
#pragma unroll
            for (int i = 0; i < 2; i++)
#pragma unroll
                for (int nb = 0; nb < 4; nb++)
                    mma_bf16(acc[i][nb], ah[i], bl[nb]);
#pragma unroll
            for (int i = 0; i < 2; i++)
#pragma unroll
                for (int nb = 0; nb < 4; nb++)
                    mma_bf16(acc[i][nb], al[i], bh[nb]);
        }
    }

    // ---- fused epilogue ----
    // acc[i][nb][e]: m-row = m0 + wm*32 + i*16 + (lane>>2) + (e>>1)*8
    //                gate = nb, h = (n0 + wn*32)/4 + 2*(lane&3) + (e&1)
    const int t = lane & 3;
    const int grow = lane >> 2;
    const int hb = ((n0 + wn * 32) >> 2) + 2 * t;

    const float alpha = alpha_p[0];
    const float rho = rho_p[0];
    const float inv_rho = 2.0f / rho;
    const float tu[2] = {tau[hb], tau[hb + 1]};
    const float sh[2] = {s[hb], s[hb + 1]};
    float bi[4][2];
#pragma unroll
    for (int g = 0; g < 4; g++) {
        bi[g][0] = bias[g * H_DIM + hb];
        bi[g][1] = bias[g * H_DIM + hb + 1];
    }

#pragma unroll
    for (int i = 0; i < 2; i++) {
#pragma unroll
        for (int rsel = 0; rsel < 2; rsel++) {
            const int r = m0 + wm * 32 + i * 16 + grow + rsel * 8;
            const float tt = time_[r];
            const float2 cx2 = *(const float2*)&cx[(size_t)r * H_DIM + hb];
            const float cxa[2] = {cx2.x, cx2.y};
            float hy2[2], cy2[2];
#pragma unroll
            for (int e = 0; e < 2; e++) {
                const int d = rsel * 2 + e;
                float gi = acc[i][0][d] + bi[0][e];
                float gf = acc[i][1][d] + bi[1][e];
                float gg = acc[i][2][d] + bi[2][e];
                float go = acc[i][3][d] + bi[3][e];
                float phi = fmodf(tt - sh[e], tu[e]) / tu[e];
                float kg;
                if (phi < 0.5f * rho)      kg = phi * inv_rho;
                else if (phi < rho)        kg = 2.0f - phi * inv_rho;
                else                       kg = alpha * phi;
                float ft = sigf(gf + 1.0f - kg);
                float it = sigf(gi) * kg;
                float gt = tanhf(gg) * kg;
                float ot = sigf(go) * kg;
                float cyv = ft * cxa[e] + it * gt;
                cy2[e] = cyv;
                hy2[e] = ot * tanhf(cyv);
            }
            *(float2*)&out[(size_t)r * H_DIM + hb] = make_float2(hy2[0], hy2[1]);
            *(float2*)&out[(size_t)B_DIM * H_DIM + (size_t)r * H_DIM + hb] =
                make_float2(cy2[0], cy2[1]);
        }
    }
}

// ---------------- launch ----------------

extern "C" void kernel_launch(void* const* d_in, const int* in_sizes, int n_in,
                              void* d_out, int out_size) {
    const float* input = (const float*)d_in[0];
    const float* time_ = (const float*)d_in[1];
    const float* hx    = (const float*)d_in[2];
    const float* cx    = (const float*)d_in[3];
    const float* Wxh_w = (const float*)d_in[4];
    const float* Wxh_b = (const float*)d_in[5];
    const float* Whh_w = (const float*)d_in[6];
    const float* tau   = (const float*)d_in[7];
    const float* s     = (const float*)d_in[8];
    const float* alpha = (const float*)d_in[9];
    const float* rho   = (const float*)d_in[10];
    float* out = (float*)d_out;

    cudaFuncSetAttribute(gemm_fused_kernel,
                         cudaFuncAttributeMaxDynamicSharedMemorySize, SMEM_BYTES);

    prep_kernel<<<6144, 256>>>(input, hx, Wxh_w, Whh_w);

    dim3 grid(NGATE / 64, B_DIM / 128);   // 64 x 32
    gemm_fused_kernel<<<grid, 256, SMEM_BYTES>>>(
        time_, cx, tau, s, alpha, rho, Wxh_b, out);
}